// round 14
// baseline (speedup 1.0000x reference)
#include <cuda_runtime.h>
#include <cuda_fp16.h>

// Problem constants
#define BATCH    8
#define S_BYTES  8192
#define NUM_EMB  384
#define BYTE_DIM 128
#define EMB_DIM  1024
#define NUM_TOK  2048
#define SCALE_F  11.313708498984761f  // sqrt(128)

// proj = SCALE * emb @ W^T, stored fp16: [NUM_EMB, EMB_DIM] (768 KB, L2-resident)
__device__ __half g_proj_h[NUM_EMB * EMB_DIM];

// ---------------------------------------------------------------------------
// Kernel 1: tiny GEMM  proj[e][n] = SCALE * sum_k emb[e][k] * W[n][k]
// M=384, N=1024, K=128. 32x32 tiles (384 blocks), full K in smem, one sync.
// fp32 math, fp16 store.
// ---------------------------------------------------------------------------
#define BM 32
#define BN 32
#define SPITCH 33

__global__ __launch_bounds__(256) void proj_gemm_kernel(const float* __restrict__ emb,
                                                        const float* __restrict__ W) {
    __shared__ float As[BYTE_DIM][SPITCH];  // [k][m]
    __shared__ float Ws[BYTE_DIM][SPITCH];  // [k][n]

    const int tid = threadIdx.x;
    const int bn = blockIdx.x & 31;   // 0..31
    const int bm = blockIdx.x >> 5;   // 0..11
    const int tx = tid & 15;
    const int ty = tid >> 4;
    const int m0 = ty * 2;
    const int n0 = tx * 2;

    const float* __restrict__ A  = emb + (size_t)(bm * BM) * BYTE_DIM;
    const float* __restrict__ Wt = W   + (size_t)(bn * BN) * BYTE_DIM;

    #pragma unroll
    for (int i = 0; i < 16; ++i) {
        int f = tid + i * 256;
        int k = f & 127;
        int r = f >> 7;
        As[k][r] = A [(size_t)r * BYTE_DIM + k];
        Ws[k][r] = Wt[(size_t)r * BYTE_DIM + k];
    }
    __syncthreads();

    float acc[2][2] = {};
    #pragma unroll 8
    for (int k = 0; k < BYTE_DIM; ++k) {
        float a0 = As[k][m0], a1 = As[k][m0 + 1];
        float w0 = Ws[k][n0], w1 = Ws[k][n0 + 1];
        acc[0][0] = fmaf(a0, w0, acc[0][0]);
        acc[0][1] = fmaf(a0, w1, acc[0][1]);
        acc[1][0] = fmaf(a1, w0, acc[1][0]);
        acc[1][1] = fmaf(a1, w1, acc[1][1]);
    }

    #pragma unroll
    for (int i = 0; i < 2; ++i) {
        __half2 h = __floats2half2_rn(acc[i][0] * SCALE_F, acc[i][1] * SCALE_F);
        *reinterpret_cast<__half2*>(
            g_proj_h + (size_t)(bm * BM + m0 + i) * EMB_DIM + bn * BN + n0) = h;
    }
}

// ---------------------------------------------------------------------------
// Warp-cooperative lower_bound over a sorted row of S_BYTES ints.
// 32-ary search, 3 rounds (step 256 -> 8 -> 1). Out-of-range probes use
// sentinels: p < 0 acts as -inf (pred true), p >= S_BYTES as +inf (pred
// false). Returns first index i with row[i] >= v, in [0, S_BYTES].
// (Validated in round 13.)
// ---------------------------------------------------------------------------
__device__ __forceinline__ int warp_lower_bound(const int* __restrict__ row,
                                                int v, int lane) {
    bool pr = row[lane << 8] < v;
    int c1 = __popc(__ballot_sync(0xffffffffu, pr));
    int base = c1 << 8;

    int p2 = base - 255 + (lane << 3);
    pr = (p2 < 0) || (row[p2] < v);
    int c2 = __popc(__ballot_sync(0xffffffffu, pr));
    int L = base + (c2 << 3) - 262;

    int p3 = L + lane;
    pr = (p3 < 0) || (p3 < S_BYTES && row[p3] < v);
    int c3 = __popc(__ballot_sync(0xffffffffu, pr) & 0xff);
    return L + c3;
}

// ---------------------------------------------------------------------------
// Kernel 2: ragged mean over fp16 proj rows, warp-per-token.
// s0 via warp 32-ary search (3 rounds); s1 via warp forward scan from s0
// (1 round typical, loop-guarded for any segment length). Gathers use
// LDG.128 (4 x uint4 per byte) — half the LSU wavefronts of the LDG.64
// version. fp32 accumulate; coalesced float4 output stores.
// grid = (NUM_TOK/8, BATCH), block = 256 (8 warps = 8 tokens).
// ---------------------------------------------------------------------------
__global__ __launch_bounds__(256) void pool_kernel(const int* __restrict__ x,
                                                   const int* __restrict__ bg,
                                                   float* __restrict__ out) {
    const int b    = blockIdx.y;
    const int wid  = threadIdx.x >> 5;
    const int lane = threadIdx.x & 31;
    const int t    = blockIdx.x * 8 + wid;

    const int* __restrict__ row = bg + (size_t)b * S_BYTES;
    const int s0 = warp_lower_bound(row, t, lane);

    // Forward scan for s1 = lower_bound(t+1), starting at s0. Sorted row ->
    // predicate is a true-prefix across lanes; popc of ballot = advance.
    int s1 = s0;
    for (;;) {
        int p = s1 + lane;
        bool pr = (p < S_BYTES) && (row[p] < t + 1);
        unsigned m = __ballot_sync(0xffffffffu, pr);
        s1 += __popc(m);
        if (m != 0xffffffffu) break;
    }
    const int cnt = s1 - s0;

    const int* __restrict__ xr = x + (size_t)b * S_BYTES;
    const uint4* __restrict__ p4 = reinterpret_cast<const uint4*>(g_proj_h);  // 128/row

    float4 acc[8];
    #pragma unroll
    for (int j = 0; j < 8; ++j) acc[j] = make_float4(0.f, 0.f, 0.f, 0.f);

    for (int s = s0; s < s1; ++s) {
        const int e = xr[s];  // warp-broadcast load, L1-hit
        const uint4* __restrict__ pr4 = p4 + (size_t)e * (EMB_DIM / 8);
        uint4 u[4];
        #pragma unroll
        for (int j = 0; j < 4; ++j) u[j] = pr4[lane + 32 * j];  // LDG.128, 512B/warp
        #pragma unroll
        for (int j = 0; j < 4; ++j) {
            float2 f0 = __half22float2(*reinterpret_cast<__half2*>(&u[j].x));
            float2 f1 = __half22float2(*reinterpret_cast<__half2*>(&u[j].y));
            float2 f2 = __half22float2(*reinterpret_cast<__half2*>(&u[j].z));
            float2 f3 = __half22float2(*reinterpret_cast<__half2*>(&u[j].w));
            acc[2 * j].x     += f0.x; acc[2 * j].y     += f0.y;
            acc[2 * j].z     += f1.x; acc[2 * j].w     += f1.y;
            acc[2 * j + 1].x += f2.x; acc[2 * j + 1].y += f2.y;
            acc[2 * j + 1].z += f3.x; acc[2 * j + 1].w += f3.y;
        }
    }

    const float inv = 1.0f / (float)(cnt > 0 ? cnt : 1);

    // uint4 j covers channels [(lane+32j)*8, +8) = float4 indices 2*(lane+32j), +1.
    float4* __restrict__ o =
        reinterpret_cast<float4*>(out) + (((size_t)b * NUM_TOK) + t) * (EMB_DIM / 4);
    #pragma unroll
    for (int j = 0; j < 4; ++j) {
        float4 v0 = make_float4(acc[2 * j].x * inv, acc[2 * j].y * inv,
                                acc[2 * j].z * inv, acc[2 * j].w * inv);
        float4 v1 = make_float4(acc[2 * j + 1].x * inv, acc[2 * j + 1].y * inv,
                                acc[2 * j + 1].z * inv, acc[2 * j + 1].w * inv);
        o[2 * (lane + 32 * j)]     = v0;
        o[2 * (lane + 32 * j) + 1] = v1;
    }
}

// ---------------------------------------------------------------------------
// Launch
// ---------------------------------------------------------------------------
extern "C" void kernel_launch(void* const* d_in, const int* in_sizes, int n_in,
                              void* d_out, int out_size) {
    const int*   x    = (const int*)  d_in[0];  // [B, S_BYTES] int32
    const int*   bg   = (const int*)  d_in[1];  // [B, S_BYTES] int32 (sorted per row)
    const float* emb  = (const float*)d_in[2];  // [NUM_EMB, BYTE_DIM] fp32
    const float* wout = (const float*)d_in[3];  // [EMB_DIM, BYTE_DIM] fp32
    float* out = (float*)d_out;                 // [B, NUM_TOK, EMB_DIM] fp32

    (void)in_sizes; (void)n_in; (void)out_size;

    proj_gemm_kernel<<<(EMB_DIM / BN) * (NUM_EMB / BM), 256>>>(emb, wout);  // 384 blocks

    dim3 pgrid(NUM_TOK / 8, BATCH);             // (256, 8) = 2048 blocks
    pool_kernel<<<pgrid, 256>>>(x, bg, out);
}

// round 15
// speedup vs baseline: 1.1306x; 1.1306x over previous
#include <cuda_runtime.h>
#include <cuda_fp16.h>

// Problem constants
#define BATCH    8
#define S_BYTES  8192
#define NUM_EMB  384
#define BYTE_DIM 128
#define EMB_DIM  1024
#define NUM_TOK  2048
#define SCALE_F  11.313708498984761f  // sqrt(128)

// proj = SCALE * emb @ W^T, stored fp16: [NUM_EMB, EMB_DIM] (768 KB, L2-resident)
__device__ __half g_proj_h[NUM_EMB * EMB_DIM];

// ---------------------------------------------------------------------------
// Kernel 1: tiny GEMM  proj[e][n] = SCALE * sum_k emb[e][k] * W[n][k]
// M=384, N=1024, K=128. 32x32 tiles (384 blocks), full K in smem, one sync.
// fp32 math, fp16 store.
// ---------------------------------------------------------------------------
#define BM 32
#define BN 32
#define SPITCH 33

__global__ __launch_bounds__(256) void proj_gemm_kernel(const float* __restrict__ emb,
                                                        const float* __restrict__ W) {
    __shared__ float As[BYTE_DIM][SPITCH];  // [k][m]
    __shared__ float Ws[BYTE_DIM][SPITCH];  // [k][n]

    const int tid = threadIdx.x;
    const int bn = blockIdx.x & 31;   // 0..31
    const int bm = blockIdx.x >> 5;   // 0..11
    const int tx = tid & 15;
    const int ty = tid >> 4;
    const int m0 = ty * 2;
    const int n0 = tx * 2;

    const float* __restrict__ A  = emb + (size_t)(bm * BM) * BYTE_DIM;
    const float* __restrict__ Wt = W   + (size_t)(bn * BN) * BYTE_DIM;

    #pragma unroll
    for (int i = 0; i < 16; ++i) {
        int f = tid + i * 256;
        int k = f & 127;
        int r = f >> 7;
        As[k][r] = A [(size_t)r * BYTE_DIM + k];
        Ws[k][r] = Wt[(size_t)r * BYTE_DIM + k];
    }
    __syncthreads();

    float acc[2][2] = {};
    #pragma unroll 8
    for (int k = 0; k < BYTE_DIM; ++k) {
        float a0 = As[k][m0], a1 = As[k][m0 + 1];
        float w0 = Ws[k][n0], w1 = Ws[k][n0 + 1];
        acc[0][0] = fmaf(a0, w0, acc[0][0]);
        acc[0][1] = fmaf(a0, w1, acc[0][1]);
        acc[1][0] = fmaf(a1, w0, acc[1][0]);
        acc[1][1] = fmaf(a1, w1, acc[1][1]);
    }

    #pragma unroll
    for (int i = 0; i < 2; ++i) {
        __half2 h = __floats2half2_rn(acc[i][0] * SCALE_F, acc[i][1] * SCALE_F);
        *reinterpret_cast<__half2*>(
            g_proj_h + (size_t)(bm * BM + m0 + i) * EMB_DIM + bn * BN + n0) = h;
    }
}

// ---------------------------------------------------------------------------
// Warp-cooperative lower_bound over a sorted row of S_BYTES ints.
// 32-ary search, 3 rounds (step 256 -> 8 -> 1). Sentinels: p < 0 acts as
// -inf (pred true), p >= S_BYTES as +inf (pred false).
// (Validated in rounds 13/14.)
// ---------------------------------------------------------------------------
__device__ __forceinline__ int warp_lower_bound(const int* __restrict__ row,
                                                int v, int lane) {
    bool pr = row[lane << 8] < v;
    int c1 = __popc(__ballot_sync(0xffffffffu, pr));
    int base = c1 << 8;

    int p2 = base - 255 + (lane << 3);
    pr = (p2 < 0) || (row[p2] < v);
    int c2 = __popc(__ballot_sync(0xffffffffu, pr));
    int L = base + (c2 << 3) - 262;

    int p3 = L + lane;
    pr = (p3 < 0) || (p3 < S_BYTES && row[p3] < v);
    int c3 = __popc(__ballot_sync(0xffffffffu, pr) & 0xff);
    return L + c3;
}

// ---------------------------------------------------------------------------
// Kernel 2: ragged mean over fp16 proj rows, warp-per-token — EXACT round-13
// champion gather/store body (LDG.64 gathers at o-index lane+32j; contiguous
// STG.128 stores), plus:
//   - s1 via warp forward scan from s0 (1 probe round typical, loop-guarded)
//   - streaming stores (__stcs): output is write-once, bypass L2 residency
// grid = (NUM_TOK/8, BATCH), block = 256 (8 warps = 8 tokens).
// ---------------------------------------------------------------------------
__global__ __launch_bounds__(256) void pool_kernel(const int* __restrict__ x,
                                                   const int* __restrict__ bg,
                                                   float* __restrict__ out) {
    const int b    = blockIdx.y;
    const int wid  = threadIdx.x >> 5;
    const int lane = threadIdx.x & 31;
    const int t    = blockIdx.x * 8 + wid;

    const int* __restrict__ row = bg + (size_t)b * S_BYTES;
    const int s0 = warp_lower_bound(row, t, lane);

    // Forward scan for s1 = lower_bound(t+1) starting at s0 (sorted row ->
    // lane predicate is a true-prefix; popc of ballot = advance).
    int s1 = s0;
    for (;;) {
        int p = s1 + lane;
        bool pr = (p < S_BYTES) && (row[p] < t + 1);
        unsigned m = __ballot_sync(0xffffffffu, pr);
        s1 += __popc(m);
        if (m != 0xffffffffu) break;
    }
    const int cnt = s1 - s0;

    const int* __restrict__ xr = x + (size_t)b * S_BYTES;
    const uint2* __restrict__ p = reinterpret_cast<const uint2*>(g_proj_h);  // 256/row

    float4 acc[8];
    #pragma unroll
    for (int j = 0; j < 8; ++j) acc[j] = make_float4(0.f, 0.f, 0.f, 0.f);

    for (int s = s0; s < s1; ++s) {
        const int e = xr[s];  // warp-broadcast load, L1-hit
        const uint2* __restrict__ pr = p + (size_t)e * (EMB_DIM / 4);
        #pragma unroll
        for (int j = 0; j < 8; ++j) {
            uint2 u = pr[lane + 32 * j];  // coalesced 256B wavefront, L2-hit
            __half2 h0 = *reinterpret_cast<__half2*>(&u.x);
            __half2 h1 = *reinterpret_cast<__half2*>(&u.y);
            float2 f0 = __half22float2(h0);
            float2 f1 = __half22float2(h1);
            acc[j].x += f0.x; acc[j].y += f0.y;
            acc[j].z += f1.x; acc[j].w += f1.y;
        }
    }

    const float inv = 1.0f / (float)(cnt > 0 ? cnt : 1);

    float4* __restrict__ o =
        reinterpret_cast<float4*>(out) + (((size_t)b * NUM_TOK) + t) * (EMB_DIM / 4);
    #pragma unroll
    for (int j = 0; j < 8; ++j) {
        float4 v = make_float4(acc[j].x * inv, acc[j].y * inv,
                               acc[j].z * inv, acc[j].w * inv);
        __stcs(&o[lane + 32 * j], v);  // contiguous STG.128.CS (evict-first)
    }
}

// ---------------------------------------------------------------------------
// Launch
// ---------------------------------------------------------------------------
extern "C" void kernel_launch(void* const* d_in, const int* in_sizes, int n_in,
                              void* d_out, int out_size) {
    const int*   x    = (const int*)  d_in[0];  // [B, S_BYTES] int32
    const int*   bg   = (const int*)  d_in[1];  // [B, S_BYTES] int32 (sorted per row)
    const float* emb  = (const float*)d_in[2];  // [NUM_EMB, BYTE_DIM] fp32
    const float* wout = (const float*)d_in[3];  // [EMB_DIM, BYTE_DIM] fp32
    float* out = (float*)d_out;                 // [B, NUM_TOK, EMB_DIM] fp32

    (void)in_sizes; (void)n_in; (void)out_size;

    proj_gemm_kernel<<<(EMB_DIM / BN) * (NUM_EMB / BM), 256>>>(emb, wout);  // 384 blocks

    dim3 pgrid(NUM_TOK / 8, BATCH);             // (256, 8) = 2048 blocks
    pool_kernel<<<pgrid, 256>>>(x, bg, out);
}